// round 2
// baseline (speedup 1.0000x reference)
#include <cuda_runtime.h>
#include <math.h>

#define TT 512
#define BBATCH 4
#define NT 2048   // BBATCH*TT tokens
#define DD 768
#define HH 12
#define HDIM 64
#define MM 3072
#define VV 32128
#define LL 6
#define NEGINF -1e10f

// ---------------- scratch (device globals; no cudaMalloc allowed) ----------------
__device__ float g_xe[NT * DD];
__device__ float g_xd[NT * DD];
__device__ float g_enc[NT * DD];
__device__ float g_h[NT * DD];
__device__ float g_q[NT * DD];
__device__ float g_k[NT * DD];
__device__ float g_v[NT * DD];
__device__ float g_ao[NT * DD];
__device__ float g_hid[NT * MM];
__device__ float g_sc[BBATCH * HH * TT * TT];
__device__ float g_bias_e[HH * TT * TT];
__device__ float g_bias_d[HH * TT * TT];
__device__ int   g_val_e[NT];
__device__ int   g_val_t[NT];

// ---------------- kernels ----------------

// C[M,N] (+)= A[M,K] * B[K,N], row-major, all dims multiples of (128,128,8)
template<bool ACC, bool RELU>
__global__ void sgemm(const float* __restrict__ A, const float* __restrict__ B,
                      float* __restrict__ C, int M, int N, int K)
{
    __shared__ float As[8][128];
    __shared__ float Bs[8][128];
    const int tid = threadIdx.x;
    const int bx = blockIdx.x, by = blockIdx.y;

    const float* Ab = A + (size_t)(by * 128) * K;
    const float* Bb = B + bx * 128;

    const int arow = tid >> 1;           // 0..127
    const int acol = (tid & 1) << 2;     // 0 or 4
    const int brow = tid >> 5;           // 0..7
    const int bcol = (tid & 31) << 2;    // 0..124
    const int tx = tid & 15, ty = tid >> 4;

    float acc[8][8];
#pragma unroll
    for (int i = 0; i < 8; i++)
#pragma unroll
        for (int j = 0; j < 8; j++) acc[i][j] = 0.f;

    for (int k0 = 0; k0 < K; k0 += 8) {
        float4 av = *(const float4*)(Ab + (size_t)arow * K + k0 + acol);
        As[acol + 0][arow] = av.x;
        As[acol + 1][arow] = av.y;
        As[acol + 2][arow] = av.z;
        As[acol + 3][arow] = av.w;
        *(float4*)(&Bs[brow][bcol]) = *(const float4*)(Bb + (size_t)(k0 + brow) * N + bcol);
        __syncthreads();
#pragma unroll
        for (int kk = 0; kk < 8; kk++) {
            float a[8], b[8];
            *(float4*)(a)     = *(const float4*)(&As[kk][ty * 8]);
            *(float4*)(a + 4) = *(const float4*)(&As[kk][ty * 8 + 4]);
            *(float4*)(b)     = *(const float4*)(&Bs[kk][tx * 8]);
            *(float4*)(b + 4) = *(const float4*)(&Bs[kk][tx * 8 + 4]);
#pragma unroll
            for (int i = 0; i < 8; i++)
#pragma unroll
                for (int j = 0; j < 8; j++) acc[i][j] += a[i] * b[j];
        }
        __syncthreads();
    }

#pragma unroll
    for (int i = 0; i < 8; i++) {
        int row = by * 128 + ty * 8 + i;
        float* Cp = C + (size_t)row * N + bx * 128 + tx * 8;
#pragma unroll
        for (int j = 0; j < 8; j++) {
            float v = acc[i][j];
            if (RELU) v = fmaxf(v, 0.f);
            if (ACC)  v += Cp[j];
            Cp[j] = v;
        }
    }
}

// S[bh,q,s] = sum_k Q[b,q,h,k]*K[b,s,h,k] + bias[h,q,s]; masked -> -1e10
__global__ void attn_scores(const float* __restrict__ Q, const float* __restrict__ K,
                            float* __restrict__ S, const float* __restrict__ bias,
                            const int* __restrict__ validQ, const int* __restrict__ validK,
                            int causal)
{
    __shared__ float Qs[HDIM][68];
    __shared__ float Ks[HDIM][68];
    const int bh = blockIdx.z;
    const int b = bh / HH, h = bh % HH;
    const int q0 = blockIdx.y * 64, s0 = blockIdx.x * 64;
    const int tid = threadIdx.x;

#pragma unroll
    for (int i = 0; i < 4; i++) {
        int e = tid + 256 * i;
        int row = e >> 4;
        int c4 = (e & 15) << 2;
        float4 qv = *(const float4*)(Q + (size_t)(b * TT + q0 + row) * DD + h * HDIM + c4);
        Qs[c4 + 0][row] = qv.x; Qs[c4 + 1][row] = qv.y;
        Qs[c4 + 2][row] = qv.z; Qs[c4 + 3][row] = qv.w;
        float4 kv = *(const float4*)(K + (size_t)(b * TT + s0 + row) * DD + h * HDIM + c4);
        Ks[c4 + 0][row] = kv.x; Ks[c4 + 1][row] = kv.y;
        Ks[c4 + 2][row] = kv.z; Ks[c4 + 3][row] = kv.w;
    }
    __syncthreads();

    const int tx = tid & 15, ty = tid >> 4;
    float acc[4][4];
#pragma unroll
    for (int i = 0; i < 4; i++)
#pragma unroll
        for (int j = 0; j < 4; j++) acc[i][j] = 0.f;

#pragma unroll 8
    for (int kk = 0; kk < HDIM; kk++) {
        float a[4], bb[4];
#pragma unroll
        for (int i = 0; i < 4; i++) a[i] = Qs[kk][ty * 4 + i];
#pragma unroll
        for (int j = 0; j < 4; j++) bb[j] = Ks[kk][tx * 4 + j];
#pragma unroll
        for (int i = 0; i < 4; i++)
#pragma unroll
            for (int j = 0; j < 4; j++) acc[i][j] += a[i] * bb[j];
    }

#pragma unroll
    for (int i = 0; i < 4; i++) {
        int q = q0 + ty * 4 + i;
#pragma unroll
        for (int j = 0; j < 4; j++) {
            int s = s0 + tx * 4 + j;
            float v = acc[i][j];
            if (bias) v += bias[((size_t)h * TT + q) * TT + s];
            bool m = validQ[b * TT + q] && validK[b * TT + s];
            if (causal && s > q) m = false;
            S[((size_t)bh * TT + q) * TT + s] = m ? v : NEGINF;
        }
    }
}

__global__ void softmax_rows(float* __restrict__ S)
{
    size_t base = (size_t)blockIdx.x * TT;
    int tid = threadIdx.x;
    float v0 = S[base + tid], v1 = S[base + tid + 256];
    __shared__ float red[256];
    red[tid] = fmaxf(v0, v1);
    __syncthreads();
    for (int o = 128; o > 0; o >>= 1) {
        if (tid < o) red[tid] = fmaxf(red[tid], red[tid + o]);
        __syncthreads();
    }
    float mx = red[0];
    __syncthreads();
    float e0 = expf(v0 - mx), e1 = expf(v1 - mx);
    red[tid] = e0 + e1;
    __syncthreads();
    for (int o = 128; o > 0; o >>= 1) {
        if (tid < o) red[tid] += red[tid + o];
        __syncthreads();
    }
    float inv = 1.0f / red[0];
    S[base + tid] = e0 * inv;
    S[base + tid + 256] = e1 * inv;
}

// O[b,q,h,k] = sum_s P[bh,q,s] * V[b,s,h,k]
__global__ void attn_pv(const float* __restrict__ P, const float* __restrict__ V,
                        float* __restrict__ O)
{
    __shared__ float Ps[64][17];
    __shared__ float Vs[16][64];
    const int bh = blockIdx.y;
    const int b = bh / HH, h = bh % HH;
    const int q0 = blockIdx.x * 64;
    const int tid = threadIdx.x;
    const int tx = tid & 15, ty = tid >> 4;

    float acc[4][4];
#pragma unroll
    for (int i = 0; i < 4; i++)
#pragma unroll
        for (int j = 0; j < 4; j++) acc[i][j] = 0.f;

    const int prow = tid >> 2, pc = (tid & 3) << 2;
    const int vrow = tid >> 4, vc = (tid & 15) << 2;

    for (int s0 = 0; s0 < TT; s0 += 16) {
        float4 pv = *(const float4*)(P + ((size_t)bh * TT + q0 + prow) * TT + s0 + pc);
        Ps[prow][pc + 0] = pv.x; Ps[prow][pc + 1] = pv.y;
        Ps[prow][pc + 2] = pv.z; Ps[prow][pc + 3] = pv.w;
        *(float4*)(&Vs[vrow][vc]) =
            *(const float4*)(V + (size_t)(b * TT + s0 + vrow) * DD + h * HDIM + vc);
        __syncthreads();
#pragma unroll
        for (int ss = 0; ss < 16; ss++) {
            float a[4], bb[4];
#pragma unroll
            for (int i = 0; i < 4; i++) a[i] = Ps[ty * 4 + i][ss];
#pragma unroll
            for (int j = 0; j < 4; j++) bb[j] = Vs[ss][tx * 4 + j];
#pragma unroll
            for (int i = 0; i < 4; i++)
#pragma unroll
                for (int j = 0; j < 4; j++) acc[i][j] += a[i] * bb[j];
        }
        __syncthreads();
    }

#pragma unroll
    for (int i = 0; i < 4; i++)
#pragma unroll
        for (int j = 0; j < 4; j++)
            O[(size_t)(b * TT + q0 + ty * 4 + i) * DD + h * HDIM + tx * 4 + j] = acc[i][j];
}

__global__ void rmsnorm_k(const float* __restrict__ X, const float* __restrict__ scale,
                          float* __restrict__ O)
{
    int row = blockIdx.x;
    int tid = threadIdx.x;
    const float* x = X + (size_t)row * DD;
    float s = 0.f;
    for (int d = tid; d < DD; d += 256) { float v = x[d]; s += v * v; }
    __shared__ float red[256];
    red[tid] = s;
    __syncthreads();
    for (int o = 128; o > 0; o >>= 1) {
        if (tid < o) red[tid] += red[tid + o];
        __syncthreads();
    }
    float r = 1.0f / sqrtf(red[0] / (float)DD + 1e-6f);
    for (int d = tid; d < DD; d += 256) O[(size_t)row * DD + d] = x[d] * r * scale[d];
}

__global__ void embed_k(const int* __restrict__ tok, const float* __restrict__ emb,
                        float* __restrict__ O)
{
    int t = blockIdx.x;
    int token = tok[t];
    const float* e = emb + (size_t)token * DD;
    for (int d = threadIdx.x; d < DD; d += 256) O[(size_t)t * DD + d] = e[d];
}

__global__ void valid_k(const int* __restrict__ tok, int* __restrict__ v, int n)
{
    int i = blockIdx.x * blockDim.x + threadIdx.x;
    if (i < n) v[i] = tok[i] > 0 ? 1 : 0;
}

__global__ void build_bias(const float* __restrict__ rel, float* __restrict__ bias, int bidir)
{
    int idx = blockIdx.x * blockDim.x + threadIdx.x;
    if (idx >= TT * TT) return;
    int q = idx / TT, s = idx % TT;
    int n = q - s;   // = -(s - q)
    int bucket;
    if (bidir) {
        int ret = (n < 0) ? 16 : 0;
        int na = n < 0 ? -n : n;
        if (na < 8) {
            bucket = ret + na;
        } else {
            int v = 8 + (int)(log((double)na / 8.0) / log(16.0) * 8.0);
            bucket = ret + (v < 15 ? v : 15);
        }
    } else {
        int na = n > 0 ? n : 0;
        if (na < 16) {
            bucket = na;
        } else {
            int v = 16 + (int)(log((double)na / 16.0) / log(8.0) * 16.0);
            bucket = (v < 31 ? v : 31);
        }
    }
#pragma unroll
    for (int h = 0; h < HH; h++)
        bias[(size_t)h * TT * TT + idx] = rel[h * 32 + bucket];
}

// ---------------- host orchestration ----------------

static void run_attention(const float* q_in, const float* kv_in,
                          const float* wq, const float* wk, const float* wv, const float* wo,
                          float* x, const float* bias,
                          const int* validQ, const int* validK, int causal,
                          float* q, float* k, float* v, float* sc, float* ao)
{
    dim3 g(DD / 128, NT / 128);
    sgemm<false, false><<<g, 256>>>(q_in, wq, q, NT, DD, DD);
    sgemm<false, false><<<g, 256>>>(kv_in, wk, k, NT, DD, DD);
    sgemm<false, false><<<g, 256>>>(kv_in, wv, v, NT, DD, DD);
    attn_scores<<<dim3(TT / 64, TT / 64, BBATCH * HH), 256>>>(q, k, sc, bias, validQ, validK, causal);
    softmax_rows<<<BBATCH * HH * TT, 256>>>(sc);
    attn_pv<<<dim3(TT / 64, BBATCH * HH), 256>>>(sc, v, ao);
    sgemm<true, false><<<g, 256>>>(ao, wo, x, NT, DD, DD);
}

extern "C" void kernel_launch(void* const* d_in, const int* in_sizes, int n_in,
                              void* d_out, int out_size)
{
    const float* emb      = (const float*)d_in[0];
    const float* rel_enc  = (const float*)d_in[1];
    const float* rel_dec  = (const float*)d_in[2];
    const float* enc_ln1  = (const float*)d_in[3];
    const float* enc_wq   = (const float*)d_in[4];
    const float* enc_wk   = (const float*)d_in[5];
    const float* enc_wv   = (const float*)d_in[6];
    const float* enc_wo   = (const float*)d_in[7];
    const float* enc_ln2  = (const float*)d_in[8];
    const float* enc_wi   = (const float*)d_in[9];
    const float* enc_wmo  = (const float*)d_in[10];
    const float* enc_norm = (const float*)d_in[11];
    const float* dec_ln1  = (const float*)d_in[12];
    const float* dec_sq   = (const float*)d_in[13];
    const float* dec_sk   = (const float*)d_in[14];
    const float* dec_sv   = (const float*)d_in[15];
    const float* dec_so   = (const float*)d_in[16];
    const float* dec_ln2  = (const float*)d_in[17];
    const float* dec_cq   = (const float*)d_in[18];
    const float* dec_ck   = (const float*)d_in[19];
    const float* dec_cv   = (const float*)d_in[20];
    const float* dec_co   = (const float*)d_in[21];
    const float* dec_ln3  = (const float*)d_in[22];
    const float* dec_wi   = (const float*)d_in[23];
    const float* dec_wmo  = (const float*)d_in[24];
    const float* dec_norm = (const float*)d_in[25];
    const float* logits_w = (const float*)d_in[26];
    const int* enc_tok    = (const int*)d_in[27];
    const int* dec_in_tok = (const int*)d_in[28];
    const int* dec_tgt    = (const int*)d_in[29];

    float *xe, *xd, *enc, *h, *q, *k, *v, *ao, *hid, *sc, *be, *bd;
    int *ve, *vt;
    cudaGetSymbolAddress((void**)&xe,  g_xe);
    cudaGetSymbolAddress((void**)&xd,  g_xd);
    cudaGetSymbolAddress((void**)&enc, g_enc);
    cudaGetSymbolAddress((void**)&h,   g_h);
    cudaGetSymbolAddress((void**)&q,   g_q);
    cudaGetSymbolAddress((void**)&k,   g_k);
    cudaGetSymbolAddress((void**)&v,   g_v);
    cudaGetSymbolAddress((void**)&ao,  g_ao);
    cudaGetSymbolAddress((void**)&hid, g_hid);
    cudaGetSymbolAddress((void**)&sc,  g_sc);
    cudaGetSymbolAddress((void**)&be,  g_bias_e);
    cudaGetSymbolAddress((void**)&bd,  g_bias_d);
    cudaGetSymbolAddress((void**)&ve,  g_val_e);
    cudaGetSymbolAddress((void**)&vt,  g_val_t);

    valid_k<<<(NT + 255) / 256, 256>>>(enc_tok, ve, NT);
    valid_k<<<(NT + 255) / 256, 256>>>(dec_tgt, vt, NT);
    build_bias<<<(TT * TT) / 256, 256>>>(rel_enc, be, 1);
    build_bias<<<(TT * TT) / 256, 256>>>(rel_dec, bd, 0);

    const size_t WS = (size_t)DD * DD;      // qkv/o weight stride per layer
    const size_t MS = (size_t)DD * MM;      // mlp weight stride per layer
    dim3 gMLP1(MM / 128, NT / 128);
    dim3 gMLP2(DD / 128, NT / 128);

    // -------- encoder --------
    embed_k<<<NT, 256>>>(enc_tok, emb, xe);
    for (int l = 0; l < LL; l++) {
        rmsnorm_k<<<NT, 256>>>(xe, enc_ln1 + (size_t)l * DD, h);
        run_attention(h, h, enc_wq + l * WS, enc_wk + l * WS, enc_wv + l * WS, enc_wo + l * WS,
                      xe, be, ve, ve, 0, q, k, v, sc, ao);
        rmsnorm_k<<<NT, 256>>>(xe, enc_ln2 + (size_t)l * DD, h);
        sgemm<false, true><<<gMLP1, 256>>>(h, enc_wi + l * MS, hid, NT, MM, DD);
        sgemm<true, false><<<gMLP2, 256>>>(hid, enc_wmo + l * MS, xe, NT, DD, MM);
    }
    rmsnorm_k<<<NT, 256>>>(xe, enc_norm, enc);

    // -------- decoder --------
    embed_k<<<NT, 256>>>(dec_in_tok, emb, xd);
    for (int l = 0; l < LL; l++) {
        rmsnorm_k<<<NT, 256>>>(xd, dec_ln1 + (size_t)l * DD, h);
        run_attention(h, h, dec_sq + l * WS, dec_sk + l * WS, dec_sv + l * WS, dec_so + l * WS,
                      xd, bd, vt, vt, 1, q, k, v, sc, ao);
        rmsnorm_k<<<NT, 256>>>(xd, dec_ln2 + (size_t)l * DD, h);
        run_attention(h, enc, dec_cq + l * WS, dec_ck + l * WS, dec_cv + l * WS, dec_co + l * WS,
                      xd, nullptr, vt, ve, 0, q, k, v, sc, ao);
        rmsnorm_k<<<NT, 256>>>(xd, dec_ln3 + (size_t)l * DD, h);
        sgemm<false, true><<<gMLP1, 256>>>(h, dec_wi + l * MS, hid, NT, MM, DD);
        sgemm<true, false><<<gMLP2, 256>>>(hid, dec_wmo + l * MS, xd, NT, DD, MM);
    }
    rmsnorm_k<<<NT, 256>>>(xd, dec_norm, h);

    // -------- logits --------
    sgemm<false, false><<<dim3(VV / 128, NT / 128), 256>>>(h, logits_w, (float*)d_out, NT, VV, DD);
}

// round 3
// speedup vs baseline: 3.3654x; 3.3654x over previous
#include <cuda_runtime.h>
#include <math.h>

#define TT 512
#define BBATCH 4
#define NT 2048   // BBATCH*TT tokens
#define DD 768
#define HH 12
#define HDIM 64
#define MM 3072
#define VV 32128
#define LL 6
#define NEGINF -1e10f
#define BK 32

// ---------------- scratch (device globals; no cudaMalloc allowed) ----------------
__device__ float g_xe[NT * DD];
__device__ float g_xd[NT * DD];
__device__ float g_enc[NT * DD];
__device__ float g_h[NT * DD];
__device__ float g_q[NT * DD];
__device__ float g_k[NT * DD];
__device__ float g_v[NT * DD];
__device__ float g_ao[NT * DD];
__device__ float g_hid[NT * MM];
__device__ float g_sc[BBATCH * HH * TT * TT];
__device__ float g_bias_e[HH * TT * TT];
__device__ float g_bias_d[HH * TT * TT];
__device__ int   g_val_e[NT];
__device__ int   g_val_t[NT];

// ---------------- low-level helpers ----------------

__device__ __forceinline__ void cp16(unsigned dst, const void* src)
{
    asm volatile("cp.async.cg.shared.global [%0], [%1], 16;\n" :: "r"(dst), "l"(src));
}
__device__ __forceinline__ void cp_commit() { asm volatile("cp.async.commit_group;\n"); }
__device__ __forceinline__ void cp_wait1()  { asm volatile("cp.async.wait_group 1;\n"); }

__device__ __forceinline__ unsigned tf32cvt(float x)
{
    unsigned y;
    asm("cvt.rna.tf32.f32 %0, %1;" : "=r"(y) : "f"(x));
    return y;
}

__device__ __forceinline__ void ldsm4(unsigned addr, unsigned* a)
{
    asm volatile("ldmatrix.sync.aligned.m8n8.x4.shared.b16 {%0,%1,%2,%3}, [%4];"
                 : "=r"(a[0]), "=r"(a[1]), "=r"(a[2]), "=r"(a[3]) : "r"(addr));
}
__device__ __forceinline__ void ldsm2(unsigned addr, unsigned* b)
{
    asm volatile("ldmatrix.sync.aligned.m8n8.x2.shared.b16 {%0,%1}, [%2];"
                 : "=r"(b[0]), "=r"(b[1]) : "r"(addr));
}

__device__ __forceinline__ void mma8(float* c, const unsigned* a, const unsigned* b)
{
    asm volatile(
        "mma.sync.aligned.m16n8k8.row.col.f32.tf32.tf32.f32 "
        "{%0,%1,%2,%3}, {%4,%5,%6,%7}, {%8,%9}, {%0,%1,%2,%3};"
        : "+f"(c[0]), "+f"(c[1]), "+f"(c[2]), "+f"(c[3])
        : "r"(a[0]), "r"(a[1]), "r"(a[2]), "r"(a[3]), "r"(b[0]), "r"(b[1]));
}

// A-tile (or NT B-tile) loader: 128 rows x 32 cols fp32, XOR-swizzled 16B chunks
__device__ __forceinline__ void load_tileA(unsigned sb, int st, const float* A,
                                           int row0, int k0, int lda, int tid)
{
#pragma unroll
    for (int j = 0; j < 4; j++) {
        int c = tid + 256 * j;
        int m = c >> 3, kc = c & 7;
        cp16(sb + st * (128 * BK * 4) + (((m << 5) | ((kc ^ (m & 7)) << 2)) << 2),
             A + (long)(row0 + m) * lda + k0 + kc * 4);
    }
}

// B-tile loader (NN): BK rows x BN cols fp32, swizzled
template<int BN>
__device__ __forceinline__ void load_tileB(unsigned sb, int st, const float* B,
                                           int n0, int k0, int ldb, int tid)
{
    constexpr int BCH = BN / 4;
    constexpr int BPT = (BK * BCH) / 256;
#pragma unroll
    for (int j = 0; j < BPT; j++) {
        int c = tid + 256 * j;
        int k = c / BCH, nc = c % BCH;
        cp16(sb + st * (BK * BN * 4) + (((k * BN) + ((nc ^ (k & 7)) << 2)) << 2),
             B + (long)(k0 + k) * ldb + n0 + nc * 4);
    }
}

// ---------------- tf32 tensor-core GEMM (NN): C[M,N] (+)= A[M,K]*B[K,N] ----------------
// BN in {128,64}. MS = M-subtiles per warp (4 for BN=128, 2 for BN=64).
template<int BN, int MS, bool ACC, bool RELU>
__global__ __launch_bounds__(256) void gemm_nn(
    const float* __restrict__ A, const float* __restrict__ B, float* __restrict__ C,
    int K, int lda, int ldb, int ldc,
    int zdiv, long az1, long az2, long bz1, long bz2, long cz1, long cz2)
{
    extern __shared__ float sm[];
    float* As = sm;                    // [2][128*BK]
    float* Bs = sm + 2 * 128 * BK;     // [2][BK*BN]
    const unsigned asb = (unsigned)__cvta_generic_to_shared(As);
    const unsigned bsb = (unsigned)__cvta_generic_to_shared(Bs);

    const int tid = threadIdx.x;
    const int lane = tid & 31, warp = tid >> 5;
    constexpr int WARPS_M = (BN == 128) ? 2 : 4;
    const int mw = (warp % WARPS_M) * (MS * 16);
    const int nw = (warp / WARPS_M) * 32;
    const int m0 = blockIdx.y * 128, n0 = blockIdx.x * BN;

    const int z = blockIdx.z;
    A += (long)(z / zdiv) * az1 + (long)(z % zdiv) * az2;
    B += (long)(z / zdiv) * bz1 + (long)(z % zdiv) * bz2;
    C += (long)(z / zdiv) * cz1 + (long)(z % zdiv) * cz2;

    float acc[MS][4][4];
#pragma unroll
    for (int i = 0; i < MS; i++)
#pragma unroll
        for (int j = 0; j < 4; j++)
#pragma unroll
            for (int q = 0; q < 4; q++) acc[i][j][q] = 0.f;

    const int nk = K / BK;
    load_tileA(asb, 0, A, m0, 0, lda, tid);
    load_tileB<BN>(bsb, 0, B, n0, 0, ldb, tid);
    cp_commit();

    for (int kt = 0; kt < nk; kt++) {
        int st = kt & 1;
        if (kt + 1 < nk) {
            load_tileA(asb, st ^ 1, A, m0, (kt + 1) * BK, lda, tid);
            load_tileB<BN>(bsb, st ^ 1, B, n0, (kt + 1) * BK, ldb, tid);
        }
        cp_commit();
        cp_wait1();
        __syncthreads();

        const unsigned ab = asb + st * (128 * BK * 4);
        const float* Bp = Bs + st * (BK * BN);

#pragma unroll
        for (int kk = 0; kk < BK; kk += 8) {
            unsigned a[MS][4];
#pragma unroll
            for (int i = 0; i < MS; i++) {
                int r = mw + 16 * i + (lane & 7) + ((lane >> 3) & 1) * 8;
                int ch = (kk >> 2) + (lane >> 4);
                ldsm4(ab + (((r << 5) | ((ch ^ (r & 7)) << 2)) << 2), a[i]);
            }
#pragma unroll
            for (int i = 0; i < MS; i++)
#pragma unroll
                for (int q = 0; q < 4; q++) a[i][q] = tf32cvt(__uint_as_float(a[i][q]));

            unsigned bf[4][2];
#pragma unroll
            for (int j = 0; j < 4; j++) {
                int n = nw + 8 * j + (lane >> 2);
                int ncc = n >> 2, nr = n & 3;
                int k1 = kk + (lane & 3);
                int k2 = k1 + 4;
                bf[j][0] = tf32cvt(Bp[k1 * BN + (((ncc ^ (k1 & 7)) << 2) | nr)]);
                bf[j][1] = tf32cvt(Bp[k2 * BN + (((ncc ^ (k2 & 7)) << 2) | nr)]);
            }
#pragma unroll
            for (int i = 0; i < MS; i++)
#pragma unroll
                for (int j = 0; j < 4; j++) mma8(acc[i][j], a[i], bf[j]);
        }
        __syncthreads();
    }

#pragma unroll
    for (int i = 0; i < MS; i++) {
        int r = m0 + mw + 16 * i + (lane >> 2);
#pragma unroll
        for (int j = 0; j < 4; j++) {
            int cn = n0 + nw + 8 * j + ((lane & 3) << 1);
            float2* p0 = (float2*)(C + (long)r * ldc + cn);
            float2* p1 = (float2*)(C + (long)(r + 8) * ldc + cn);
            float2 v0 = make_float2(acc[i][j][0], acc[i][j][1]);
            float2 v1 = make_float2(acc[i][j][2], acc[i][j][3]);
            if (RELU) {
                v0.x = fmaxf(v0.x, 0.f); v0.y = fmaxf(v0.y, 0.f);
                v1.x = fmaxf(v1.x, 0.f); v1.y = fmaxf(v1.y, 0.f);
            }
            if (ACC) {
                float2 o0 = *p0, o1 = *p1;
                v0.x += o0.x; v0.y += o0.y; v1.x += o1.x; v1.y += o1.y;
            }
            *p0 = v0; *p1 = v1;
        }
    }
}

// ---------------- tf32 attention scores (NT): S = Q*K^T + bias, masked ----------------
__global__ __launch_bounds__(256) void attn_scores_tc(
    const float* __restrict__ Q, const float* __restrict__ Km, float* __restrict__ S,
    const float* __restrict__ bias, const int* __restrict__ validQ,
    const int* __restrict__ validK, int causal)
{
    extern __shared__ float sm[];
    float* As = sm;                     // [2][128*32]
    float* Bs = sm + 2 * 128 * BK;      // [2][128*32]
    const unsigned asb = (unsigned)__cvta_generic_to_shared(As);
    const unsigned bsb = (unsigned)__cvta_generic_to_shared(Bs);

    const int tid = threadIdx.x;
    const int lane = tid & 31, warp = tid >> 5;
    const int mw = (warp & 1) * 64;
    const int nw = (warp >> 1) * 32;
    const int m0 = blockIdx.y * 128, n0 = blockIdx.x * 128;

    const int z = blockIdx.z;
    const int b = z / HH, h = z % HH;
    const float* Ap = Q + (long)b * TT * DD + h * HDIM;
    const float* Bp = Km + (long)b * TT * DD + h * HDIM;

    float acc[4][4][4];
#pragma unroll
    for (int i = 0; i < 4; i++)
#pragma unroll
        for (int j = 0; j < 4; j++)
#pragma unroll
            for (int q = 0; q < 4; q++) acc[i][j][q] = 0.f;

    const int nk = HDIM / BK;   // 2
    load_tileA(asb, 0, Ap, m0, 0, DD, tid);
    load_tileA(bsb, 0, Bp, n0, 0, DD, tid);
    cp_commit();

    for (int kt = 0; kt < nk; kt++) {
        int st = kt & 1;
        if (kt + 1 < nk) {
            load_tileA(asb, st ^ 1, Ap, m0, (kt + 1) * BK, DD, tid);
            load_tileA(bsb, st ^ 1, Bp, n0, (kt + 1) * BK, DD, tid);
        }
        cp_commit();
        cp_wait1();
        __syncthreads();

        const unsigned ab = asb + st * (128 * BK * 4);
        const unsigned bb = bsb + st * (128 * BK * 4);

#pragma unroll
        for (int kk = 0; kk < BK; kk += 8) {
            unsigned a[4][4];
#pragma unroll
            for (int i = 0; i < 4; i++) {
                int r = mw + 16 * i + (lane & 7) + ((lane >> 3) & 1) * 8;
                int ch = (kk >> 2) + (lane >> 4);
                ldsm4(ab + (((r << 5) | ((ch ^ (r & 7)) << 2)) << 2), a[i]);
            }
#pragma unroll
            for (int i = 0; i < 4; i++)
#pragma unroll
                for (int q = 0; q < 4; q++) a[i][q] = tf32cvt(__uint_as_float(a[i][q]));

            unsigned bf[4][2];
#pragma unroll
            for (int j = 0; j < 4; j++) {
                int r = nw + 8 * j + (lane & 7);
                int ch = (kk >> 2) + ((lane >> 3) & 1);
                ldsm2(bb + (((r << 5) | ((ch ^ (r & 7)) << 2)) << 2), bf[j]);
                bf[j][0] = tf32cvt(__uint_as_float(bf[j][0]));
                bf[j][1] = tf32cvt(__uint_as_float(bf[j][1]));
            }
#pragma unroll
            for (int i = 0; i < 4; i++)
#pragma unroll
                for (int j = 0; j < 4; j++) mma8(acc[i][j], a[i], bf[j]);
        }
        __syncthreads();
    }

    const long sbase = (long)z * TT * TT;
#pragma unroll
    for (int i = 0; i < 4; i++) {
        int q0 = m0 + mw + 16 * i + (lane >> 2);
#pragma unroll
        for (int j = 0; j < 4; j++) {
            int s0 = n0 + nw + 8 * j + ((lane & 3) << 1);
#pragma unroll
            for (int rr = 0; rr < 2; rr++) {
                int q = q0 + rr * 8;
                int vq = validQ[b * TT + q];
#pragma unroll
                for (int cc = 0; cc < 2; cc++) {
                    int s = s0 + cc;
                    float v = acc[i][j][rr * 2 + cc];
                    if (bias) v += bias[(long)h * TT * TT + (long)q * TT + s];
                    bool m = vq && validK[b * TT + s] && (!causal || s <= q);
                    S[sbase + (long)q * TT + s] = m ? v : NEGINF;
                }
            }
        }
    }
}

// ---------------- elementwise / reduction kernels ----------------

__global__ void softmax_rows(float* __restrict__ S)
{
    size_t base = (size_t)blockIdx.x * TT;
    int tid = threadIdx.x;
    float v0 = S[base + tid], v1 = S[base + tid + 256];
    __shared__ float red[256];
    red[tid] = fmaxf(v0, v1);
    __syncthreads();
    for (int o = 128; o > 0; o >>= 1) {
        if (tid < o) red[tid] = fmaxf(red[tid], red[tid + o]);
        __syncthreads();
    }
    float mx = red[0];
    __syncthreads();
    float e0 = expf(v0 - mx), e1 = expf(v1 - mx);
    red[tid] = e0 + e1;
    __syncthreads();
    for (int o = 128; o > 0; o >>= 1) {
        if (tid < o) red[tid] += red[tid + o];
        __syncthreads();
    }
    float inv = 1.0f / red[0];
    S[base + tid] = e0 * inv;
    S[base + tid + 256] = e1 * inv;
}

__global__ void rmsnorm_k(const float* __restrict__ X, const float* __restrict__ scale,
                          float* __restrict__ O)
{
    int row = blockIdx.x;
    int tid = threadIdx.x;
    const float* x = X + (size_t)row * DD;
    float s = 0.f;
    for (int d = tid; d < DD; d += 256) { float v = x[d]; s += v * v; }
    __shared__ float red[256];
    red[tid] = s;
    __syncthreads();
    for (int o = 128; o > 0; o >>= 1) {
        if (tid < o) red[tid] += red[tid + o];
        __syncthreads();
    }
    float r = 1.0f / sqrtf(red[0] / (float)DD + 1e-6f);
    for (int d = tid; d < DD; d += 256) O[(size_t)row * DD + d] = x[d] * r * scale[d];
}

__global__ void embed_k(const int* __restrict__ tok, const float* __restrict__ emb,
                        float* __restrict__ O)
{
    int t = blockIdx.x;
    int token = tok[t];
    const float* e = emb + (size_t)token * DD;
    for (int d = threadIdx.x; d < DD; d += 256) O[(size_t)t * DD + d] = e[d];
}

__global__ void valid_k(const int* __restrict__ tok, int* __restrict__ v, int n)
{
    int i = blockIdx.x * blockDim.x + threadIdx.x;
    if (i < n) v[i] = tok[i] > 0 ? 1 : 0;
}

__global__ void build_bias(const float* __restrict__ rel, float* __restrict__ bias, int bidir)
{
    int idx = blockIdx.x * blockDim.x + threadIdx.x;
    if (idx >= TT * TT) return;
    int q = idx / TT, s = idx % TT;
    int n = q - s;
    int bucket;
    if (bidir) {
        int ret = (n < 0) ? 16 : 0;
        int na = n < 0 ? -n : n;
        if (na < 8) {
            bucket = ret + na;
        } else {
            int v = 8 + (int)(log((double)na / 8.0) / log(16.0) * 8.0);
            bucket = ret + (v < 15 ? v : 15);
        }
    } else {
        int na = n > 0 ? n : 0;
        if (na < 16) {
            bucket = na;
        } else {
            int v = 16 + (int)(log((double)na / 16.0) / log(8.0) * 16.0);
            bucket = (v < 31 ? v : 31);
        }
    }
#pragma unroll
    for (int h = 0; h < HH; h++)
        bias[(size_t)h * TT * TT + idx] = rel[h * 32 + bucket];
}

// ---------------- host orchestration ----------------

#define SMEM_NN128 ((2 * 128 * BK + 2 * BK * 128) * 4)   // 65536
#define SMEM_NN64  ((2 * 128 * BK + 2 * BK * 64) * 4)    // 49152
#define SMEM_NT    ((2 * 128 * BK + 2 * 128 * BK) * 4)   // 65536

static void set_attrs()
{
    cudaFuncSetAttribute(gemm_nn<128, 4, false, false>, cudaFuncAttributeMaxDynamicSharedMemorySize, SMEM_NN128);
    cudaFuncSetAttribute(gemm_nn<128, 4, true,  false>, cudaFuncAttributeMaxDynamicSharedMemorySize, SMEM_NN128);
    cudaFuncSetAttribute(gemm_nn<128, 4, false, true >, cudaFuncAttributeMaxDynamicSharedMemorySize, SMEM_NN128);
    cudaFuncSetAttribute(gemm_nn<64,  2, false, false>, cudaFuncAttributeMaxDynamicSharedMemorySize, SMEM_NN64);
    cudaFuncSetAttribute(attn_scores_tc, cudaFuncAttributeMaxDynamicSharedMemorySize, SMEM_NT);
}

static void run_attention(const float* q_in, const float* kv_in,
                          const float* wq, const float* wk, const float* wv, const float* wo,
                          float* x, const float* bias,
                          const int* validQ, const int* validK, int causal,
                          float* q, float* k, float* v, float* sc, float* ao)
{
    dim3 g(DD / 128, NT / 128, 1);
    gemm_nn<128, 4, false, false><<<g, 256, SMEM_NN128>>>(q_in, wq, q, DD, DD, DD, DD, 1, 0, 0, 0, 0, 0, 0);
    gemm_nn<128, 4, false, false><<<g, 256, SMEM_NN128>>>(kv_in, wk, k, DD, DD, DD, DD, 1, 0, 0, 0, 0, 0, 0);
    gemm_nn<128, 4, false, false><<<g, 256, SMEM_NN128>>>(kv_in, wv, v, DD, DD, DD, DD, 1, 0, 0, 0, 0, 0, 0);

    attn_scores_tc<<<dim3(TT / 128, TT / 128, BBATCH * HH), 256, SMEM_NT>>>(
        q, k, sc, bias, validQ, validK, causal);
    softmax_rows<<<BBATCH * HH * TT, 256>>>(sc);

    // PV: O[b,q,h,:] = P[bh] * V[b,:,h,:]
    gemm_nn<64, 2, false, false><<<dim3(1, TT / 128, BBATCH * HH), 256, SMEM_NN64>>>(
        sc, v, ao, TT, TT, DD, DD, HH,
        (long)HH * TT * TT, (long)TT * TT,
        (long)TT * DD, 64,
        (long)TT * DD, 64);

    gemm_nn<128, 4, true, false><<<g, 256, SMEM_NN128>>>(ao, wo, x, DD, DD, DD, DD, 1, 0, 0, 0, 0, 0, 0);
}

extern "C" void kernel_launch(void* const* d_in, const int* in_sizes, int n_in,
                              void* d_out, int out_size)
{
    const float* emb      = (const float*)d_in[0];
    const float* rel_enc  = (const float*)d_in[1];
    const float* rel_dec  = (const float*)d_in[2];
    const float* enc_ln1  = (const float*)d_in[3];
    const float* enc_wq   = (const float*)d_in[4];
    const float* enc_wk   = (const float*)d_in[5];
    const float* enc_wv   = (const float*)d_in[6];
    const float* enc_wo   = (const float*)d_in[7];
    const float* enc_ln2  = (const float*)d_in[8];
    const float* enc_wi   = (const float*)d_in[9];
    const float* enc_wmo  = (const float*)d_in[10];
    const float* enc_norm = (const float*)d_in[11];
    const float* dec_ln1  = (const float*)d_in[12];
    const float* dec_sq   = (const float*)d_in[13];
    const float* dec_sk   = (const float*)d_in[14];
    const float* dec_sv   = (const float*)d_in[15];
    const float* dec_so   = (const float*)d_in[16];
    const float* dec_ln2  = (const float*)d_in[17];
    const float* dec_cq   = (const float*)d_in[18];
    const float* dec_ck   = (const float*)d_in[19];
    const float* dec_cv   = (const float*)d_in[20];
    const float* dec_co   = (const float*)d_in[21];
    const float* dec_ln3  = (const float*)d_in[22];
    const float* dec_wi   = (const float*)d_in[23];
    const float* dec_wmo  = (const float*)d_in[24];
    const float* dec_norm = (const float*)d_in[25];
    const float* logits_w = (const float*)d_in[26];
    const int* enc_tok    = (const int*)d_in[27];
    const int* dec_in_tok = (const int*)d_in[28];
    const int* dec_tgt    = (const int*)d_in[29];

    float *xe, *xd, *enc, *h, *q, *k, *v, *ao, *hid, *sc, *be, *bd;
    int *ve, *vt;
    cudaGetSymbolAddress((void**)&xe,  g_xe);
    cudaGetSymbolAddress((void**)&xd,  g_xd);
    cudaGetSymbolAddress((void**)&enc, g_enc);
    cudaGetSymbolAddress((void**)&h,   g_h);
    cudaGetSymbolAddress((void**)&q,   g_q);
    cudaGetSymbolAddress((void**)&k,   g_k);
    cudaGetSymbolAddress((void**)&v,   g_v);
    cudaGetSymbolAddress((void**)&ao,  g_ao);
    cudaGetSymbolAddress((void**)&hid, g_hid);
    cudaGetSymbolAddress((void**)&sc,  g_sc);
    cudaGetSymbolAddress((void**)&be,  g_bias_e);
    cudaGetSymbolAddress((void**)&bd,  g_bias_d);
    cudaGetSymbolAddress((void**)&ve,  g_val_e);
    cudaGetSymbolAddress((void**)&vt,  g_val_t);

    set_attrs();

    valid_k<<<(NT + 255) / 256, 256>>>(enc_tok, ve, NT);
    valid_k<<<(NT + 255) / 256, 256>>>(dec_tgt, vt, NT);
    build_bias<<<(TT * TT) / 256, 256>>>(rel_enc, be, 1);
    build_bias<<<(TT * TT) / 256, 256>>>(rel_dec, bd, 0);

    const size_t WS = (size_t)DD * DD;
    const size_t MS_ = (size_t)DD * MM;
    dim3 gMLP1(MM / 128, NT / 128, 1);
    dim3 gMLP2(DD / 128, NT / 128, 1);

    // -------- encoder --------
    embed_k<<<NT, 256>>>(enc_tok, emb, xe);
    for (int l = 0; l < LL; l++) {
        rmsnorm_k<<<NT, 256>>>(xe, enc_ln1 + (size_t)l * DD, h);
        run_attention(h, h, enc_wq + l * WS, enc_wk + l * WS, enc_wv + l * WS, enc_wo + l * WS,
                      xe, be, ve, ve, 0, q, k, v, sc, ao);
        rmsnorm_k<<<NT, 256>>>(xe, enc_ln2 + (size_t)l * DD, h);
        gemm_nn<128, 4, false, true><<<gMLP1, 256, SMEM_NN128>>>(h, enc_wi + l * MS_, hid, DD, DD, MM, MM, 1, 0, 0, 0, 0, 0, 0);
        gemm_nn<128, 4, true, false><<<gMLP2, 256, SMEM_NN128>>>(hid, enc_wmo + l * MS_, xe, MM, MM, DD, DD, 1, 0, 0, 0, 0, 0, 0);
    }
    rmsnorm_k<<<NT, 256>>>(xe, enc_norm, enc);

    // -------- decoder --------
    embed_k<<<NT, 256>>>(dec_in_tok, emb, xd);
    for (int l = 0; l < LL; l++) {
        rmsnorm_k<<<NT, 256>>>(xd, dec_ln1 + (size_t)l * DD, h);
        run_attention(h, h, dec_sq + l * WS, dec_sk + l * WS, dec_sv + l * WS, dec_so + l * WS,
                      xd, bd, vt, vt, 1, q, k, v, sc, ao);
        rmsnorm_k<<<NT, 256>>>(xd, dec_ln2 + (size_t)l * DD, h);
        run_attention(h, enc, dec_cq + l * WS, dec_ck + l * WS, dec_cv + l * WS, dec_co + l * WS,
                      xd, nullptr, vt, ve, 0, q, k, v, sc, ao);
        rmsnorm_k<<<NT, 256>>>(xd, dec_ln3 + (size_t)l * DD, h);
        gemm_nn<128, 4, false, true><<<gMLP1, 256, SMEM_NN128>>>(h, dec_wi + l * MS_, hid, DD, DD, MM, MM, 1, 0, 0, 0, 0, 0, 0);
        gemm_nn<128, 4, true, false><<<gMLP2, 256, SMEM_NN128>>>(hid, dec_wmo + l * MS_, xd, MM, MM, DD, DD, 1, 0, 0, 0, 0, 0, 0);
    }
    rmsnorm_k<<<NT, 256>>>(xd, dec_norm, h);

    // -------- logits --------
    gemm_nn<128, 4, false, false><<<dim3(VV / 128, NT / 128, 1), 256, SMEM_NN128>>>(
        h, logits_w, (float*)d_out, DD, DD, VV, VV, 1, 0, 0, 0, 0, 0, 0);
}